// round 17
// baseline (speedup 1.0000x reference)
#include <cuda_runtime.h>
#include <cuda_bf16.h>
#include <math.h>
#include <stdint.h>

#define Bn 2
#define Cn 8
#define Fn 256
#define Wn 512
#define Hn 8
#define HDn 32
#define En 4
#define NB (Bn*Cn*Fn*Wn)
#define WOFF (Cn*Fn*Fn)
#define NHEAD (Bn*Cn*Hn)
#define QS ((size_t)NHEAD*Wn*16)
#define VS ((size_t)NHEAD*Wn*HDn)
#define AS ((size_t)Bn*Cn*Wn*Fn)

// ======================= warp-MMA helpers (baseline PTX, sm_80+) =======================
__device__ __forceinline__ uint32_t smem_u32(const void* p) {
    uint32_t a;
    asm("{ .reg .u64 t; cvta.to.shared.u64 t, %1; cvt.u32.u64 %0, t; }" : "=r"(a) : "l"(p));
    return a;
}
__device__ __forceinline__ void ldm_x4(uint32_t& r0, uint32_t& r1, uint32_t& r2, uint32_t& r3,
                                       uint32_t addr) {
    asm volatile("ldmatrix.sync.aligned.m8n8.x4.shared.b16 {%0,%1,%2,%3}, [%4];"
                 : "=r"(r0), "=r"(r1), "=r"(r2), "=r"(r3) : "r"(addr));
}
__device__ __forceinline__ void ldm_x2_trans(uint32_t& r0, uint32_t& r1, uint32_t addr) {
    asm volatile("ldmatrix.sync.aligned.m8n8.x2.trans.shared.b16 {%0,%1}, [%2];"
                 : "=r"(r0), "=r"(r1) : "r"(addr));
}
__device__ __forceinline__ void mma_bf16(float* d, const uint32_t* a, const uint32_t* b) {
    asm volatile("mma.sync.aligned.m16n8k16.row.col.f32.bf16.bf16.f32 "
                 "{%0,%1,%2,%3}, {%4,%5,%6,%7}, {%8,%9}, {%0,%1,%2,%3};"
                 : "+f"(d[0]), "+f"(d[1]), "+f"(d[2]), "+f"(d[3])
                 : "r"(a[0]), "r"(a[1]), "r"(a[2]), "r"(a[3]), "r"(b[0]), "r"(b[1]));
}
__device__ __forceinline__ uint32_t pack_split(float a, float b, uint32_t& lo) {
    __nv_bfloat16 ha = __float2bfloat16(a), hb = __float2bfloat16(b);
    __nv_bfloat16 la = __float2bfloat16(a - __bfloat162float(ha));
    __nv_bfloat16 lb = __float2bfloat16(b - __bfloat162float(hb));
    lo = (uint32_t)__bfloat16_as_ushort(la) | ((uint32_t)__bfloat16_as_ushort(lb) << 16);
    return (uint32_t)__bfloat16_as_ushort(ha) | ((uint32_t)__bfloat16_as_ushort(hb) << 16);
}
__device__ __forceinline__ uint32_t packbf(float a, float b) {
    __nv_bfloat162 v = __floats2bfloat162_rn(a, b);
    return *(uint32_t*)&v;
}

// ======================= scratch (device globals) =======================
__device__ float g_h[NB];
__device__ float g_lin6[6*NB];
__device__ float g_t1[NB];
__device__ float g_ffn[Bn*Cn*En*Wn];
__device__ uint2 g_qI[2*NHEAD*Wn*16];
__device__ uint2 g_kI[2*NHEAD*Wn*16];
__device__ __nv_bfloat16 g_vbf[2*NHEAD*Wn*HDn];
__device__ __nv_bfloat16 g_zTh[Bn*Cn*Wn*Fn];
__device__ __nv_bfloat16 g_zTl[Bn*Cn*Wn*Fn];
__device__ __nv_bfloat16 g_skTh[Bn*Cn*Wn*Fn];
__device__ __nv_bfloat16 g_skTl[Bn*Cn*Wn*Fn];
__device__ __nv_bfloat16 g_atTh[2*Bn*Cn*Wn*Fn];
__device__ __nv_bfloat16 g_atTl[2*Bn*Cn*Wn*Fn];
__device__ __nv_bfloat16 g_WqH[4*WOFF];
__device__ __nv_bfloat16 g_WkH[4*WOFF];
__device__ __nv_bfloat16 g_WvH[4*WOFF];
__device__ __nv_bfloat16 g_WoH[4*WOFF];

// ============ LayerNorm -> transposed bf16 hi/lo; grid (32, 16), blk 256 = 16w x 16fg ============
__global__ void __launch_bounds__(256) ln_t_v4(const float* __restrict__ X,
                                               const float* __restrict__ gam,
                                               const float* __restrict__ bet,
                                               __nv_bfloat16* __restrict__ Zh,
                                               __nv_bfloat16* __restrict__ Zl) {
    __shared__ float ps[16][17], ps2[16][17], mb[16], ib[16];
    int tid = threadIdx.x, w = tid & 15, fg = tid >> 4;
    int bc = blockIdx.y, c = bc & (Cn - 1);
    int w0 = blockIdx.x * 16;
    const float* xp = X + (size_t)bc * Fn * Wn + w0 + w;
    float s = 0.f, s2 = 0.f;
#pragma unroll 4
    for (int f = fg * 16; f < fg * 16 + 16; f++) {
        float v = xp[(size_t)f * Wn];
        s += v; s2 += v * v;
    }
    ps[fg][w] = s; ps2[fg][w] = s2;
    __syncthreads();
    if (tid < 16) {
        float S = 0.f, S2 = 0.f;
#pragma unroll
        for (int g = 0; g < 16; g++) { S += ps[g][tid]; S2 += ps2[g][tid]; }
        float m = S * (1.0f / Fn);
        mb[tid] = m;
        ib[tid] = rsqrtf(S2 * (1.0f / Fn) - m * m + 1e-5f);
    }
    __syncthreads();
    float m = mb[w], inv = ib[w];
    const float* gp = gam + c * Fn;
    const float* bp = bet + c * Fn;
    __nv_bfloat16* th = Zh + ((size_t)bc * Wn + w0 + w) * Fn;
    __nv_bfloat16* tl = Zl + ((size_t)bc * Wn + w0 + w) * Fn;
    for (int f0 = fg * 16; f0 < fg * 16 + 16; f0 += 8) {
        uint32_t ph[4], pl[4];
#pragma unroll
        for (int j = 0; j < 4; j++) {
            int f = f0 + 2 * j;
            float v0 = (xp[(size_t)f * Wn]     - m) * inv * gp[f]   + bp[f];
            float v1 = (xp[(size_t)(f+1) * Wn] - m) * inv * gp[f+1] + bp[f+1];
            ph[j] = pack_split(v0, v1, pl[j]);
        }
        *(uint4*)(th + f0) = make_uint4(ph[0], ph[1], ph[2], ph[3]);
        *(uint4*)(tl + f0) = make_uint4(pl[0], pl[1], pl[2], pl[3]);
    }
}

// ============ transpose + split: (b,c,f,w) fp32 -> [bc][w][f] bf16 hi/lo ============
__global__ void tsplit_kernel(const float* __restrict__ X,
                              __nv_bfloat16* __restrict__ Th, __nv_bfloat16* __restrict__ Tl) {
    __shared__ float t[32][33];
    int bc = blockIdx.z;
    int w0 = blockIdx.x * 32, f0 = blockIdx.y * 32;
    const float* xp = X + ((size_t)bc * Fn + f0) * Wn + w0;
#pragma unroll
    for (int i = 0; i < 4; i++) {
        int fr = threadIdx.y + i * 8;
        t[fr][threadIdx.x] = xp[(size_t)fr * Wn + threadIdx.x];
    }
    __syncthreads();
#pragma unroll
    for (int i = 0; i < 4; i++) {
        int wr = threadIdx.y + i * 8;
        float v = t[threadIdx.x][wr];
        __nv_bfloat16 h = __float2bfloat16(v);
        __nv_bfloat16 l = __float2bfloat16(v - __bfloat162float(h));
        size_t idx = ((size_t)bc * Wn + w0 + wr) * Fn + f0 + threadIdx.x;
        Th[idx] = h; Tl[idx] = l;
    }
}

// ============ weight split: bf16-hi only ============
__global__ void wsplit_all(const float* __restrict__ S0, const float* __restrict__ S1,
                           const float* __restrict__ S2, const float* __restrict__ S3,
                           __nv_bfloat16* H0, __nv_bfloat16* H1,
                           __nv_bfloat16* H2, __nv_bfloat16* H3) {
    int which = blockIdx.y;
    const float* X = which == 0 ? S0 : which == 1 ? S1 : which == 2 ? S2 : S3;
    __nv_bfloat16* H = which == 0 ? H0 : which == 1 ? H1 : which == 2 ? H2 : H3;
    int i = (blockIdx.x * 256 + threadIdx.x) * 4;
    float4 v = *(const float4*)(X + i);
    uint32_t h0 = packbf(v.x, v.y);
    uint32_t h1 = packbf(v.z, v.w);
    *(uint2*)((unsigned short*)H + i) = make_uint2(h0, h1);
}

// ========== 2-term bf16 GEMM body: A_hi(direct-gmem frags) x (B_hi + B_lo)(smem) ==========
#define KCn 64
#define LDT 72
#define TELEM (128 * LDT)
#define GSM (2 * TELEM * 2)          // 36864 bytes (2 tiles: Bh, Bl)

template<bool ACC>
__device__ __forceinline__ void gemm_body(const __nv_bfloat16* __restrict__ gAh,
                                          const __nv_bfloat16* __restrict__ gBh,
                                          const __nv_bfloat16* __restrict__ gBl,
                                          float* __restrict__ Yrow) {
    extern __shared__ __nv_bfloat16 sm[];
    int tid = threadIdx.x, lane = tid & 31, wid = tid >> 5;
    int wm = wid >> 2, wn = wid & 3;

    float acc[4][4][4] = {};
    int lrow = tid >> 1;
    int lq   = (tid & 1) * 4;

    uint32_t sb = smem_u32(sm);
    int grp = lane >> 3, lr = lane & 7;
    int bRow = wn * 32 + (grp >> 1) * 8 + lr;
    int bCol = (grp & 1) * 8;

    const __nv_bfloat16* aBase = gAh + (size_t)(wm * 64 + (lane >> 2)) * Fn + (lane & 3) * 2;

    for (int kc = 0; kc < 4; kc++) {
        if (kc) __syncthreads();
        const uint4* pc = (const uint4*)(gBh + (size_t)lrow * Fn + kc * KCn);
        const uint4* pd = (const uint4*)(gBl + (size_t)lrow * Fn + kc * KCn);
        uint4* qc = (uint4*)(sm + lrow * LDT);
        uint4* qd = (uint4*)(sm + TELEM + lrow * LDT);
#pragma unroll
        for (int j = 0; j < 4; j++) {
            qc[lq + j] = pc[lq + j];
            qd[lq + j] = pd[lq + j];
        }
        __syncthreads();
#pragma unroll
        for (int ks = 0; ks < 4; ks++) {
            int k0 = kc * KCn + ks * 16;
            uint32_t ah[4][4], bh[2][4], bl[2][4];
#pragma unroll
            for (int mi = 0; mi < 4; mi++) {
                const __nv_bfloat16* ap = aBase + (size_t)(mi * 16) * Fn + k0;
                ah[mi][0] = *(const uint32_t*)ap;
                ah[mi][1] = *(const uint32_t*)(ap + 8 * Fn);
                ah[mi][2] = *(const uint32_t*)(ap + 8);
                ah[mi][3] = *(const uint32_t*)(ap + 8 * Fn + 8);
            }
#pragma unroll
            for (int nb = 0; nb < 2; nb++) {
                uint32_t off = ((bRow + nb * 16) * LDT + bCol + ks * 16) * 2;
                ldm_x4(bh[nb][0], bh[nb][1], bh[nb][2], bh[nb][3], sb + off);
                ldm_x4(bl[nb][0], bl[nb][1], bl[nb][2], bl[nb][3], sb + TELEM * 2 + off);
            }
#pragma unroll
            for (int mi = 0; mi < 4; mi++) {
#pragma unroll
                for (int nb = 0; nb < 2; nb++) {
                    mma_bf16(acc[mi][2*nb],   ah[mi], &bh[nb][0]);
                    mma_bf16(acc[mi][2*nb+1], ah[mi], &bh[nb][2]);
                    mma_bf16(acc[mi][2*nb],   ah[mi], &bl[nb][0]);
                    mma_bf16(acc[mi][2*nb+1], ah[mi], &bl[nb][2]);
                }
            }
        }
    }

#pragma unroll
    for (int mi = 0; mi < 4; mi++) {
        int row = wm * 64 + mi * 16 + (lane >> 2);
#pragma unroll
        for (int ni = 0; ni < 4; ni++) {
            int col = wn * 32 + ni * 8 + (lane & 3) * 2;
            float* p0 = Yrow + (size_t)row * Wn + col;
            float* p1 = p0 + 8 * Wn;
            float2 v0 = make_float2(acc[mi][ni][0], acc[mi][ni][1]);
            float2 v1 = make_float2(acc[mi][ni][2], acc[mi][ni][3]);
            if (ACC) {
                float2 o0 = *(const float2*)p0, o1 = *(const float2*)p1;
                v0.x += o0.x; v0.y += o0.y; v1.x += o1.x; v1.y += o1.y;
            }
            *(float2*)p0 = v0;
            *(float2*)p1 = v1;
        }
    }
}

// Q/K/V projection GEMM, pair-capable: grid (4, 2, 48*NPAIR); z = pair*48 + which*16 + bc
__global__ void __launch_bounds__(256) gemm_qkv(
        const __nv_bfloat16* __restrict__ WqH_,
        const __nv_bfloat16* __restrict__ WkH_,
        const __nv_bfloat16* __restrict__ WvH_,
        const __nv_bfloat16* __restrict__ th, const __nv_bfloat16* __restrict__ tl,
        const __nv_bfloat16* __restrict__ m0h, const __nv_bfloat16* __restrict__ m0l,
        const __nv_bfloat16* __restrict__ m1h, const __nv_bfloat16* __restrict__ m1l,
        float* __restrict__ dst6) {
    int z = blockIdx.z;
    int pair = z / 48, inner = z % 48;
    int which = inner >> 4, bc = inner & 15, c = bc & (Cn - 1);
    int tileM = blockIdx.y * 128, tileN = blockIdx.x * 128;
    size_t wofs = (size_t)pair * WOFF + ((size_t)c * Fn + tileM) * Fn;
    const __nv_bfloat16* Ah = (which == 0 ? WqH_ : which == 1 ? WkH_ : WvH_) + wofs;
    const __nv_bfloat16* Bh = (which == 0 ? th : (pair == 0 ? m0h : m1h)) + ((size_t)bc * Wn + tileN) * Fn;
    const __nv_bfloat16* Bl = (which == 0 ? tl : (pair == 0 ? m0l : m1l)) + ((size_t)bc * Wn + tileN) * Fn;
    float* Y = dst6 + ((size_t)pair * 3 + which) * NB + ((size_t)bc * Fn + tileM) * Wn + tileN;
    gemm_body<false>(Ah, Bh, Bl, Y);
}

// Wo GEMM over NP pairs: Y = Ybase + sum of pair GEMMs
template<int NP>
__global__ void __launch_bounds__(256) gemm_woN(
        const __nv_bfloat16* __restrict__ AhG,
        const __nv_bfloat16* __restrict__ BhG, const __nv_bfloat16* __restrict__ BlG,
        const float* __restrict__ Ybase, float* __restrict__ Y) {
    extern __shared__ __nv_bfloat16 sm[];
    int bc = blockIdx.z, c = bc & (Cn - 1);
    int tileM = blockIdx.y * 128, tileN = blockIdx.x * 128;
    int tid = threadIdx.x, lane = tid & 31, wid = tid >> 5;
    int wm = wid >> 2, wn = wid & 3;
    float acc[4][4][4] = {};
    int lrow = tid >> 1;
    int lq   = (tid & 1) * 4;
    uint32_t sb = smem_u32(sm);
    int grp = lane >> 3, lr = lane & 7;
    int bRow = wn * 32 + (grp >> 1) * 8 + lr;
    int bCol = (grp & 1) * 8;

#pragma unroll
    for (int pp = 0; pp < NP; pp++) {
        const __nv_bfloat16* gAh = AhG + (size_t)pp * WOFF + ((size_t)c * Fn + tileM) * Fn;
        const __nv_bfloat16* gBh = BhG + (size_t)pp * AS + ((size_t)bc * Wn + tileN) * Fn;
        const __nv_bfloat16* gBl = BlG + (size_t)pp * AS + ((size_t)bc * Wn + tileN) * Fn;
        const __nv_bfloat16* aBase = gAh + (size_t)(wm * 64 + (lane >> 2)) * Fn + (lane & 3) * 2;
        for (int kc = 0; kc < 4; kc++) {
            if (pp || kc) __syncthreads();
            const uint4* pc = (const uint4*)(gBh + (size_t)lrow * Fn + kc * KCn);
            const uint4* pd = (const uint4*)(gBl + (size_t)lrow * Fn + kc * KCn);
            uint4* qc = (uint4*)(sm + lrow * LDT);
            uint4* qd = (uint4*)(sm + TELEM + lrow * LDT);
#pragma unroll
            for (int j = 0; j < 4; j++) {
                qc[lq + j] = pc[lq + j];
                qd[lq + j] = pd[lq + j];
            }
            __syncthreads();
#pragma unroll
            for (int ks = 0; ks < 4; ks++) {
                int k0 = kc * KCn + ks * 16;
                uint32_t ah[4][4], bh[2][4], bl[2][4];
#pragma unroll
                for (int mi = 0; mi < 4; mi++) {
                    const __nv_bfloat16* ap = aBase + (size_t)(mi * 16) * Fn + k0;
                    ah[mi][0] = *(const uint32_t*)ap;
                    ah[mi][1] = *(const uint32_t*)(ap + 8 * Fn);
                    ah[mi][2] = *(const uint32_t*)(ap + 8);
                    ah[mi][3] = *(const uint32_t*)(ap + 8 * Fn + 8);
                }
#pragma unroll
                for (int nb = 0; nb < 2; nb++) {
                    uint32_t off = ((bRow + nb * 16) * LDT + bCol + ks * 16) * 2;
                    ldm_x4(bh[nb][0], bh[nb][1], bh[nb][2], bh[nb][3], sb + off);
                    ldm_x4(bl[nb][0], bl[nb][1], bl[nb][2], bl[nb][3], sb + TELEM * 2 + off);
                }
#pragma unroll
                for (int mi = 0; mi < 4; mi++) {
#pragma unroll
                    for (int nb = 0; nb < 2; nb++) {
                        mma_bf16(acc[mi][2*nb],   ah[mi], &bh[nb][0]);
                        mma_bf16(acc[mi][2*nb+1], ah[mi], &bh[nb][2]);
                        mma_bf16(acc[mi][2*nb],   ah[mi], &bl[nb][0]);
                        mma_bf16(acc[mi][2*nb+1], ah[mi], &bl[nb][2]);
                    }
                }
            }
        }
    }

    size_t base = ((size_t)bc * Fn + tileM) * Wn + tileN;
    const float* Brow = Ybase + base;
    float* Yrow = Y + base;
#pragma unroll
    for (int mi = 0; mi < 4; mi++) {
        int row = wm * 64 + mi * 16 + (lane >> 2);
#pragma unroll
        for (int ni = 0; ni < 4; ni++) {
            int col = wn * 32 + ni * 8 + (lane & 3) * 2;
            const float* b0 = Brow + (size_t)row * Wn + col;
            const float* b1 = b0 + 8 * Wn;
            float* p0 = Yrow + (size_t)row * Wn + col;
            float* p1 = p0 + 8 * Wn;
            float2 o0 = *(const float2*)b0, o1 = *(const float2*)b1;
            o0.x += acc[mi][ni][0]; o0.y += acc[mi][ni][1];
            o1.x += acc[mi][ni][2]; o1.y += acc[mi][ni][3];
            *(float2*)p0 = o0;
            *(float2*)p1 = o1;
        }
    }
}

// ======= conv3+bias (+RoPE) for Q/K/V, pair-capable: grid (4, 128, 6*NPAIR) =======
__global__ void __launch_bounds__(128) conv_qkv(const float* __restrict__ lin6,
                                                const float* __restrict__ KqG, const float* __restrict__ bqG,
                                                const float* __restrict__ KkG, const float* __restrict__ bkG,
                                                const float* __restrict__ KvG, const float* __restrict__ bvG,
                                                int i0,
                                                uint2* __restrict__ qI, uint2* __restrict__ kI,
                                                __nv_bfloat16* __restrict__ vbf) {
    __shared__ float sIn[Cn][2][132];
    __shared__ float ks[Cn * Cn * 3];
    int tid = threadIdx.x;
    int zz = blockIdx.z;
    int pair = zz / 6, r = zz % 6;
    int which = r >> 1, b = r & 1;
    int i = i0 + pair;
    const float* Lin = lin6 + ((size_t)pair * 3 + which) * NB;
    const float* Kc  = (which == 0 ? KqG : which == 1 ? KkG : KvG) + (size_t)i * Cn * Cn * 3;
    const float* bias = (which == 0 ? bqG : which == 1 ? bkG : bvG) + i * Cn;
    int w0 = blockIdx.x * 128;
    int p  = blockIdx.y;
    int f0 = 2 * p;
    for (int t = tid; t < Cn * 2 * 130; t += 128) {
        int ci = t / 260, rr = t % 260;
        int fi = rr / 130, wo = rr % 130;
        int gw = w0 + wo - 1;
        float v = (gw >= 0 && gw < Wn) ? Lin[((size_t)(b*Cn + ci) * Fn + f0 + fi) * Wn + gw] : 0.f;
        sIn[ci][fi][wo] = v;
    }
    for (int t = tid; t < Cn * Cn * 3; t += 128) ks[t] = Kc[t];
    __syncthreads();

    int w = w0 + tid;
    float cs = 1.f, sn = 0.f;
    if (which < 2) {
        int j = p & 15;
        float invf = exp10f(-0.25f * (float)j);
        sincosf((float)w * invf, &sn, &cs);
    }
    int h  = p >> 4;
    int jj = p & 15;
#pragma unroll
    for (int co = 0; co < Cn; co++) {
        float acc0 = bias[co], acc1 = acc0;
#pragma unroll
        for (int ci = 0; ci < Cn; ci++) {
            float k0 = ks[co*24 + ci*3], k1 = ks[co*24 + ci*3 + 1], k2 = ks[co*24 + ci*3 + 2];
            acc0 += k0 * sIn[ci][0][tid] + k1 * sIn[ci][0][tid+1] + k2 * sIn[ci][0][tid+2];
            acc1 += k0 * sIn[ci][1][tid] + k1 * sIn[ci][1][tid+1] + k2 * sIn[ci][1][tid+2];
        }
        size_t head = (size_t)(b*Cn + co) * Hn + h;
        size_t idx = (head * Wn + w) * 16 + jj;
        if (which < 2) {
            float o0 = acc0 * cs - acc1 * sn;
            float o1 = acc1 * cs + acc0 * sn;
            uint32_t lo, hi = pack_split(o0, o1, lo);
            (which == 0 ? qI : kI)[pair * QS + idx] = make_uint2(hi, lo);
        } else {
            ((__nv_bfloat162*)vbf)[pair * (VS/2) + idx] = __floats2bfloat162_rn(acc0, acc1);
        }
    }
}

// ========== tensor-core flash attention (2-term QK), register-prefetched staging ==========
__global__ void __launch_bounds__(256, 1) attn_mma(const uint2* __restrict__ Qi,
                                                   const uint2* __restrict__ Ki,
                                                   const __nv_bfloat16* __restrict__ Vg,
                                                   __nv_bfloat16* __restrict__ AttH,
                                                   __nv_bfloat16* __restrict__ AttL) {
    __shared__ __nv_bfloat16 Kh[64][40];
    __shared__ __nv_bfloat16 Kl[64][40];
    __shared__ __nv_bfloat16 Vs[64][40];
    int pair = blockIdx.x >> 8, rest = blockIdx.x & 255;
    int head = rest >> 1, half = rest & 1;
    int tid = threadIdx.x, lane = tid & 31, wid = tid >> 5;
    int qb = half * 256 + wid * 32;
    size_t hbase = (size_t)head * Wn;
    Qi += pair * QS; Ki += pair * QS; Vg += pair * VS;
    AttH += pair * AS; AttL += pair * AS;

    uint32_t qh[2][2][4];
#pragma unroll
    for (int mi = 0; mi < 2; mi++) {
        int r0 = qb + mi * 16 + (lane >> 2);
#pragma unroll
        for (int kk = 0; kk < 2; kk++) {
            int jp = kk * 8 + (lane & 3);
            qh[mi][kk][0] = Qi[(hbase + r0) * 16 + jp].x;
            qh[mi][kk][1] = Qi[(hbase + r0 + 8) * 16 + jp].x;
            qh[mi][kk][2] = Qi[(hbase + r0) * 16 + jp + 4].x;
            qh[mi][kk][3] = Qi[(hbase + r0 + 8) * 16 + jp + 4].x;
        }
    }
    float m_[4] = {-1e30f, -1e30f, -1e30f, -1e30f};
    float l_[4] = {0.f, 0.f, 0.f, 0.f};
    float o[2][4][4] = {};
    uint32_t sbK = smem_u32(Kh), sbKl = smem_u32(Kl), sbV = smem_u32(Vs);
    int grp = lane >> 3, lr = lane & 7;
    int rowV = tid >> 2, qV = tid & 3;

    uint2 kreg[4];
    uint4 vreg;
#pragma unroll
    for (int it = 0; it < 4; it++) {
        int idx = tid + it * 256;
        kreg[it] = Ki[(hbase + (idx >> 4)) * 16 + (idx & 15)];
    }
    vreg = ((const uint4*)(Vg + (hbase + rowV) * HDn))[qV];

    for (int kt = 0; kt < 8; kt++) {
#pragma unroll
        for (int it = 0; it < 4; it++) {
            int idx = tid + it * 256;
            int row = idx >> 4, j = idx & 15;
            ((uint32_t*)&Kh[row][0])[j] = kreg[it].x;
            ((uint32_t*)&Kl[row][0])[j] = kreg[it].y;
        }
        *((uint4*)&Vs[rowV][qV * 8]) = vreg;
        __syncthreads();
        if (kt < 7) {
            int kb = (kt + 1) * 64;
#pragma unroll
            for (int it = 0; it < 4; it++) {
                int idx = tid + it * 256;
                kreg[it] = Ki[(hbase + kb + (idx >> 4)) * 16 + (idx & 15)];
            }
            vreg = ((const uint4*)(Vg + (hbase + kb + rowV) * HDn))[qV];
        }

        float s[2][8][4] = {};
#pragma unroll
        for (int kk = 0; kk < 2; kk++) {
#pragma unroll
            for (int nb = 0; nb < 4; nb++) {
                uint32_t kh4[4], kl4[4];
                uint32_t off = ((nb * 16 + (grp >> 1) * 8 + lr) * 40 + (grp & 1) * 8 + kk * 16) * 2;
                ldm_x4(kh4[0], kh4[1], kh4[2], kh4[3], sbK + off);
                ldm_x4(kl4[0], kl4[1], kl4[2], kl4[3], sbKl + off);
#pragma unroll
                for (int mi = 0; mi < 2; mi++) {
                    mma_bf16(s[mi][2*nb],   qh[mi][kk], &kh4[0]);
                    mma_bf16(s[mi][2*nb+1], qh[mi][kk], &kh4[2]);
                    mma_bf16(s[mi][2*nb],   qh[mi][kk], &kl4[0]);
                    mma_bf16(s[mi][2*nb+1], qh[mi][kk], &kl4[2]);
                }
            }
        }

        uint32_t pa[2][4][4];
#pragma unroll
        for (int mi = 0; mi < 2; mi++) {
            float mx0 = -1e30f, mx1 = -1e30f;
#pragma unroll
            for (int n = 0; n < 8; n++) {
#pragma unroll
                for (int q = 0; q < 4; q++) s[mi][n][q] *= 0.0625f;
                mx0 = fmaxf(mx0, fmaxf(s[mi][n][0], s[mi][n][1]));
                mx1 = fmaxf(mx1, fmaxf(s[mi][n][2], s[mi][n][3]));
            }
            mx0 = fmaxf(mx0, __shfl_xor_sync(0xffffffffu, mx0, 1));
            mx0 = fmaxf(mx0, __shfl_xor_sync(0xffffffffu, mx0, 2));
            mx1 = fmaxf(mx1, __shfl_xor_sync(0xffffffffu, mx1, 1));
            mx1 = fmaxf(mx1, __shfl_xor_sync(0xffffffffu, mx1, 2));
            int si = mi * 2;
            float mn0 = fmaxf(m_[si], mx0), mn1 = fmaxf(m_[si+1], mx1);
            float c0 = __expf(m_[si] - mn0), c1 = __expf(m_[si+1] - mn1);
            m_[si] = mn0; m_[si+1] = mn1;
            float ls0 = 0.f, ls1 = 0.f;
#pragma unroll
            for (int n = 0; n < 8; n++) {
                float p0 = __expf(s[mi][n][0] - mn0);
                float p1 = __expf(s[mi][n][1] - mn0);
                float p2 = __expf(s[mi][n][2] - mn1);
                float p3 = __expf(s[mi][n][3] - mn1);
                ls0 += p0 + p1; ls1 += p2 + p3;
                s[mi][n][0] = p0; s[mi][n][1] = p1; s[mi][n][2] = p2; s[mi][n][3] = p3;
            }
            ls0 += __shfl_xor_sync(0xffffffffu, ls0, 1);
            ls0 += __shfl_xor_sync(0xffffffffu, ls0, 2);
            ls1 += __shfl_xor_sync(0xffffffffu, ls1, 1);
            ls1 += __shfl_xor_sync(0xffffffffu, ls1, 2);
            l_[si]   = l_[si]   * c0 + ls0;
            l_[si+1] = l_[si+1] * c1 + ls1;
#pragma unroll
            for (int dn = 0; dn < 4; dn++) {
                o[mi][dn][0] *= c0; o[mi][dn][1] *= c0;
                o[mi][dn][2] *= c1; o[mi][dn][3] *= c1;
            }
#pragma unroll
            for (int t = 0; t < 4; t++) {
                pa[mi][t][0] = packbf(s[mi][2*t][0],   s[mi][2*t][1]);
                pa[mi][t][1] = packbf(s[mi][2*t][2],   s[mi][2*t][3]);
                pa[mi][t][2] = packbf(s[mi][2*t+1][0], s[mi][2*t+1][1]);
                pa[mi][t][3] = packbf(s[mi][2*t+1][2], s[mi][2*t+1][3]);
            }
        }

#pragma unroll
        for (int dn = 0; dn < 4; dn++) {
            uint32_t vb[4][2];
#pragma unroll
            for (int t = 0; t < 4; t++) {
                uint32_t off = ((t * 16 + (lane & 15)) * 40 + dn * 8) * 2;
                ldm_x2_trans(vb[t][0], vb[t][1], sbV + off);
            }
#pragma unroll
            for (int mi = 0; mi < 2; mi++)
#pragma unroll
                for (int t = 0; t < 4; t++)
                    mma_bf16(o[mi][dn], pa[mi][t], vb[t]);
        }
        __syncthreads();
    }

    int bc = head >> 3, hh = head & 7;
#pragma unroll
    for (int mi = 0; mi < 2; mi++) {
        int r0 = qb + mi * 16 + (lane >> 2);
        float i0 = 1.0f / l_[mi*2], i1 = 1.0f / l_[mi*2 + 1];
#pragma unroll
        for (int dn = 0; dn < 4; dn++) {
            int d0 = dn * 8 + (lane & 3) * 2;
            size_t a0 = ((size_t)bc * Wn + r0) * Fn + hh * HDn + d0;
            size_t a1 = ((size_t)bc * Wn + r0 + 8) * Fn + hh * HDn + d0;
            uint32_t lo0, hi0 = pack_split(o[mi][dn][0] * i0, o[mi][dn][1] * i0, lo0);
            uint32_t lo1, hi1 = pack_split(o[mi][dn][2] * i1, o[mi][dn][3] * i1, lo1);
            *(uint32_t*)(AttH + a0) = hi0;
            *(uint32_t*)(AttL + a0) = lo0;
            *(uint32_t*)(AttH + a1) = hi1;
            *(uint32_t*)(AttL + a1) = lo1;
        }
    }
}

// ============ fused LN + depthwise convs (k11 sq_relu + k7) — proven ============
__global__ void __launch_bounds__(256) lnconv_ab(const float* __restrict__ X,
                                                 const float* __restrict__ gam,
                                                 const float* __restrict__ bet,
                                                 const float* __restrict__ k11, const float* __restrict__ b11,
                                                 const float* __restrict__ k7,  const float* __restrict__ b7,
                                                 float* __restrict__ Yo) {
    extern __shared__ float sZ[];
    __shared__ float gs[Fn], bs[Fn], ps[4][64], ps2[4][64], mb[64], ib[64];
    int tid = threadIdx.x, w = tid & 63, fg = tid >> 6;
    int bc = blockIdx.y, c = bc & (Cn - 1);
    int w0 = blockIdx.x * 64;
    const float* xp = X + (size_t)bc * Fn * Wn + w0;
    for (int i = tid; i < Fn * 64; i += 256)
        sZ[i] = xp[(size_t)(i >> 6) * Wn + (i & 63)];
    for (int i = tid; i < Fn; i += 256) { gs[i] = gam[c * Fn + i]; bs[i] = bet[c * Fn + i]; }
    __syncthreads();
    float s = 0.f, s2 = 0.f;
#pragma unroll 4
    for (int f = fg * 64; f < fg * 64 + 64; f++) {
        float v = sZ[f * 64 + w];
        s += v; s2 += v * v;
    }
    ps[fg][w] = s; ps2[fg][w] = s2;
    __syncthreads();
    if (fg == 0) {
        float S  = ps[0][w]  + ps[1][w]  + ps[2][w]  + ps[3][w];
        float S2 = ps2[0][w] + ps2[1][w] + ps2[2][w] + ps2[3][w];
        float m = S * (1.0f / Fn);
        mb[w] = m;
        ib[w] = rsqrtf(S2 * (1.0f / Fn) - m * m + 1e-5f);
    }
    __syncthreads();
    float m = mb[w], inv = ib[w];
#pragma unroll 4
    for (int f = fg * 64; f < fg * 64 + 64; f++)
        sZ[f * 64 + w] = (sZ[f * 64 + w] - m) * inv * gs[f] + bs[f];
    __syncthreads();
    float wk11[11], wk7[7];
#pragma unroll
    for (int t = 0; t < 11; t++) wk11[t] = k11[c * 11 + t];
#pragma unroll
    for (int t = 0; t < 7; t++)  wk7[t]  = k7[c * 7 + t];
    float bb11 = b11[c], bb7 = b7[c];
    float* yo = Yo + (size_t)bc * Fn * Wn + w0 + w;
    for (int f = fg * 64; f < fg * 64 + 64; f++) {
        float a = bb11;
#pragma unroll
        for (int t = 0; t < 11; t++) {
            int ff = f - 5 + t;
            if (ff >= 0 && ff < Fn) a += sZ[ff * 64 + w] * wk11[t];
        }
        a = fmaxf(a, 0.f); a = a * a;
        float bo = bb7;
#pragma unroll
        for (int t = 0; t < 7; t++) {
            int ff = f - 3 + t;
            if (ff >= 0 && ff < Fn) bo += sZ[ff * 64 + w] * wk7[t];
        }
        yo[(size_t)f * Wn] = a + bo;
    }
}

// ============ fused LN + k7 conv + residual add into H — proven ============
__global__ void __launch_bounds__(256) lnconv2_add(const float* __restrict__ X,
                                                   const float* __restrict__ gam,
                                                   const float* __restrict__ bet,
                                                   const float* __restrict__ k7, const float* __restrict__ b7,
                                                   float* __restrict__ Hb) {
    extern __shared__ float sZ[];
    __shared__ float gs[Fn], bs[Fn], ps[4][64], ps2[4][64], mb[64], ib[64];
    int tid = threadIdx.x, w = tid & 63, fg = tid >> 6;
    int bc = blockIdx.y, c = bc & (Cn - 1);
    int w0 = blockIdx.x * 64;
    const float* xp = X + (size_t)bc * Fn * Wn + w0;
    for (int i = tid; i < Fn * 64; i += 256)
        sZ[i] = xp[(size_t)(i >> 6) * Wn + (i & 63)];
    for (int i = tid; i < Fn; i += 256) { gs[i] = gam[c * Fn + i]; bs[i] = bet[c * Fn + i]; }
    __syncthreads();
    float s = 0.f, s2 = 0.f;
#pragma unroll 4
    for (int f = fg * 64; f < fg * 64 + 64; f++) {
        float v = sZ[f * 64 + w];
        s += v; s2 += v * v;
    }
    ps[fg][w] = s; ps2[fg][w] = s2;
    __syncthreads();
    if (fg == 0) {
        float S  = ps[0][w]  + ps[1][w]  + ps[2][w]  + ps[3][w];
        float S2 = ps2[0][w] + ps2[1][w] + ps2[2][w] + ps2[3][w];
        float m = S * (1.0f / Fn);
        mb[w] = m;
        ib[w] = rsqrtf(S2 * (1.0f / Fn) - m * m + 1e-5f);
    }
    __syncthreads();
    float m = mb[w], inv = ib[w];
#pragma unroll 4
    for (int f = fg * 64; f < fg * 64 + 64; f++)
        sZ[f * 64 + w] = (sZ[f * 64 + w] - m) * inv * gs[f] + bs[f];
    __syncthreads();
    float wk7[7];
#pragma unroll
    for (int t = 0; t < 7; t++) wk7[t] = k7[c * 7 + t];
    float bb7 = b7[c];
    float* hb = Hb + (size_t)bc * Fn * Wn + w0 + w;
    for (int f = fg * 64; f < fg * 64 + 64; f++) {
        float v = bb7;
#pragma unroll
        for (int t = 0; t < 7; t++) {
            int ff = f - 3 + t;
            if (ff >= 0 && ff < Fn) v += sZ[ff * 64 + w] * wk7[t];
        }
        hb[(size_t)f * Wn] += v;
    }
}

// ============ fused LN + FFN first layer ============
__global__ void __launch_bounds__(256) ln_ffn3(const float* __restrict__ X,
                                               const float* __restrict__ gam,
                                               const float* __restrict__ bet,
                                               const float* __restrict__ w3,
                                               float* __restrict__ T) {
    extern __shared__ float sZ[];
    __shared__ float ws[En * Fn], gs[Fn], bs[Fn];
    __shared__ float ps[4][64], ps2[4][64], mb[64], ib[64];
    __shared__ float pacc[4][En][64];
    int tid = threadIdx.x, w = tid & 63, fg = tid >> 6;
    int bc = blockIdx.y, c = bc & (Cn - 1);
    int w0 = blockIdx.x * 64;
    const float* xp = X + (size_t)bc * Fn * Wn + w0;
    for (int i = tid; i < Fn * 64; i += 256)
        sZ[i] = xp[(size_t)(i >> 6) * Wn + (i & 63)];
    for (int i = tid; i < En * Fn; i += 256) ws[i] = w3[c * En * Fn + i];
    for (int i = tid; i < Fn; i += 256) { gs[i] = gam[c * Fn + i]; bs[i] = bet[c * Fn + i]; }
    __syncthreads();
    float s = 0.f, s2 = 0.f;
#pragma unroll 4
    for (int f = fg * 64; f < fg * 64 + 64; f++) {
        float v = sZ[f * 64 + w];
        s += v; s2 += v * v;
    }
    ps[fg][w] = s; ps2[fg][w] = s2;
    __syncthreads();
    if (fg == 0) {
        float S  = ps[0][w]  + ps[1][w]  + ps[2][w]  + ps[3][w];
        float S2 = ps2[0][w] + ps2[1][w] + ps2[2][w] + ps2[3][w];
        float m = S * (1.0f / Fn);
        mb[w] = m;
        ib[w] = rsqrtf(S2 * (1.0f / Fn) - m * m + 1e-5f);
    }
    __syncthreads();
    float m = mb[w], inv = ib[w];
    float acc[En] = {};
#pragma unroll 4
    for (int f = fg * 64; f < fg * 64 + 64; f++) {
        float zn = (sZ[f * 64 + w] - m) * inv * gs[f] + bs[f];
#pragma unroll
        for (int e = 0; e < En; e++) acc[e] += zn * ws[e * Fn + f];
    }
#pragma unroll
    for (int e = 0; e < En; e++) pacc[fg][e][w] = acc[e];
    __syncthreads();
    if (fg == 0) {
        float* tp = T + (size_t)bc * En * Wn + w0 + w;
#pragma unroll
        for (int e = 0; e < En; e++) {
            float v = pacc[0][e][w] + pacc[1][e][w] + pacc[2][e][w] + pacc[3][e][w];
            v = fmaxf(v, 0.f);
            tp[(size_t)e * Wn] = v * v;
        }
    }
}

// ============ fused FFN second layer + residual + concat output ============
__global__ void ffn4_write(const float* __restrict__ T, const float* __restrict__ w4,
                           const float* __restrict__ Hb, const float* __restrict__ X,
                           float* __restrict__ O) {
    int idx = blockIdx.x * 256 + threadIdx.x;
    int w  = idx & (Wn - 1);
    int f  = (idx >> 9) & (Fn - 1);
    int bc = idx >> 17;
    int c  = bc & (Cn - 1);
    const float* tp = T + (size_t)bc * En * Wn + w;
    const float* wp = w4 + ((size_t)c * Fn + f) * En;
    float v = tp[0] * wp[0] + tp[Wn] * wp[1] + tp[2 * Wn] * wp[2] + tp[3 * Wn] * wp[3];
    float h = Hb[idx] + v;
    int b = idx / (Cn * Fn * Wn);
    int r = idx - b * (Cn * Fn * Wn);
    O[(size_t)b * 2 * Cn * Fn * Wn + r] = X[idx];
    O[(size_t)b * 2 * Cn * Fn * Wn + Cn * Fn * Wn + r] = h;
}

// =====================================================================================

extern "C" void kernel_launch(void* const* d_in, const int* in_sizes, int n_in,
                              void* d_out, int out_size) {
    const float* x     = (const float*)d_in[0];
    const float* skip  = (const float*)d_in[1];
    const float* Wq    = (const float*)d_in[2];
    const float* Kq    = (const float*)d_in[3];
    const float* bq    = (const float*)d_in[4];
    const float* Wk    = (const float*)d_in[5];
    const float* Kk    = (const float*)d_in[6];
    const float* bk    = (const float*)d_in[7];
    const float* Wv    = (const float*)d_in[8];
    const float* Kv    = (const float*)d_in[9];
    const float* bv    = (const float*)d_in[10];
    const float* Wo    = (const float*)d_in[11];
    const float* ng    = (const float*)d_in[12];
    const float* nbet  = (const float*)d_in[13];
    const float* c1a_w = (const float*)d_in[14];
    const float* c1a_b = (const float*)d_in[15];
    const float* c1b_w = (const float*)d_in[16];
    const float* c1b_b = (const float*)d_in[17];
    const float* c2_w  = (const float*)d_in[18];
    const float* c2_b  = (const float*)d_in[19];
    const float* w3    = (const float*)d_in[20];
    const float* w4    = (const float*)d_in[21];
    float* out = (float*)d_out;

    float *hB, *lin6B, *t1B, *ffnB;
    cudaGetSymbolAddress((void**)&hB,    g_h);
    cudaGetSymbolAddress((void**)&lin6B, g_lin6);
    cudaGetSymbolAddress((void**)&t1B,   g_t1);
    cudaGetSymbolAddress((void**)&ffnB,  g_ffn);
    uint2 *qI, *kI;
    __nv_bfloat16 *vBf;
    cudaGetSymbolAddress((void**)&qI,  g_qI);
    cudaGetSymbolAddress((void**)&kI,  g_kI);
    cudaGetSymbolAddress((void**)&vBf, g_vbf);
    __nv_bfloat16 *zTh, *zTl, *skTh, *skTl, *atTh, *atTl;
    __nv_bfloat16 *WqH, *WkH, *WvH, *WoH;
    cudaGetSymbolAddress((void**)&zTh,  g_zTh);  cudaGetSymbolAddress((void**)&zTl,  g_zTl);
    cudaGetSymbolAddress((void**)&skTh, g_skTh); cudaGetSymbolAddress((void**)&skTl, g_skTl);
    cudaGetSymbolAddress((void**)&atTh, g_atTh); cudaGetSymbolAddress((void**)&atTl, g_atTl);
    cudaGetSymbolAddress((void**)&WqH, g_WqH);
    cudaGetSymbolAddress((void**)&WkH, g_WkH);
    cudaGetSymbolAddress((void**)&WvH, g_WvH);
    cudaGetSymbolAddress((void**)&WoH, g_WoH);

    const int TSM = Fn * 64 * 4;
    cudaFuncSetAttribute(gemm_qkv,    cudaFuncAttributeMaxDynamicSharedMemorySize, GSM);
    cudaFuncSetAttribute(gemm_woN<1>, cudaFuncAttributeMaxDynamicSharedMemorySize, GSM);
    cudaFuncSetAttribute(gemm_woN<2>, cudaFuncAttributeMaxDynamicSharedMemorySize, GSM);
    cudaFuncSetAttribute(lnconv_ab,   cudaFuncAttributeMaxDynamicSharedMemorySize, TSM);
    cudaFuncSetAttribute(lnconv2_add, cudaFuncAttributeMaxDynamicSharedMemorySize, TSM);
    cudaFuncSetAttribute(ln_ffn3,     cudaFuncAttributeMaxDynamicSharedMemorySize, TSM);

    const int nElemBlocks = NB / 256;
    const int wBlocks = (4 * WOFF) / 1024;
    const dim3 gLN(Wn / 16, Bn * Cn);
    const dim3 gT64(Wn / 64, Bn * Cn);

    wsplit_all<<<dim3(wBlocks, 4), 256>>>(Wq, Wk, Wv, Wo, WqH, WkH, WvH, WoH);
    tsplit_kernel<<<dim3(Wn/32, Fn/32, Bn*Cn), dim3(32, 8)>>>(skip, skTh, skTl);

    auto run_ln_t = [&](const float* X, int gi) {
        ln_t_v4<<<gLN, 256>>>(X, ng + gi * Cn * Fn, nbet + gi * Cn * Fn, zTh, zTl);
    };

    // --- att0 + att1 as one batched pair; h = x + both (seeded inside Wo GEMM) ---
    run_ln_t(x, 0);
    gemm_qkv<<<dim3(4, 2, 96), 256, GSM>>>(WqH, WkH, WvH,
                                           zTh, zTl, zTh, zTl, skTh, skTl, lin6B);
    conv_qkv<<<dim3(4, 128, 12), 128>>>(lin6B, Kq, bq, Kk, bk, Kv, bv, 0, qI, kI, vBf);
    attn_mma<<<512, 256>>>(qI, kI, vBf, atTh, atTl);
    gemm_woN<2><<<dim3(4, 2, 16), 256, GSM>>>(WoH, atTh, atTl, x, hB);

    // conv block (proven two-kernel form)
    lnconv_ab<<<gT64, 256, TSM>>>(hB, ng + 1 * Cn * Fn, nbet + 1 * Cn * Fn,
                                  c1a_w, c1a_b, c1b_w, c1b_b, t1B);
    lnconv2_add<<<gT64, 256, TSM>>>(t1B, ng + 2 * Cn * Fn, nbet + 2 * Cn * Fn,
                                    c2_w, c2_b, hB);

    // h += att2(LN3(h), same)
    run_ln_t(hB, 3);
    gemm_qkv<<<dim3(4, 2, 48), 256, GSM>>>(WqH + 2*(size_t)WOFF, WkH + 2*(size_t)WOFF,
                                           WvH + 2*(size_t)WOFF,
                                           zTh, zTl, zTh, zTl, zTh, zTl, lin6B);
    conv_qkv<<<dim3(4, 128, 6), 128>>>(lin6B, Kq, bq, Kk, bk, Kv, bv, 2, qI, kI, vBf);
    attn_mma<<<256, 256>>>(qI, kI, vBf, atTh, atTl);
    gemm_woN<1><<<dim3(4, 2, 16), 256, GSM>>>(WoH + 2*(size_t)WOFF, atTh, atTl, hB, hB);

    // h += att3(LN4(h), skip)
    run_ln_t(hB, 4);
    gemm_qkv<<<dim3(4, 2, 48), 256, GSM>>>(WqH + 3*(size_t)WOFF, WkH + 3*(size_t)WOFF,
                                           WvH + 3*(size_t)WOFF,
                                           zTh, zTl, skTh, skTl, skTh, skTl, lin6B);
    conv_qkv<<<dim3(4, 128, 6), 128>>>(lin6B, Kq, bq, Kk, bk, Kv, bv, 3, qI, kI, vBf);
    attn_mma<<<256, 256>>>(qI, kI, vBf, atTh, atTl);
    gemm_woN<1><<<dim3(4, 2, 16), 256, GSM>>>(WoH + 3*(size_t)WOFF, atTh, atTl, hB, hB);

    // FFN (LN5 fused into ffn3; ffn4 fused with concat output)
    ln_ffn3<<<gT64, 256, TSM>>>(hB, ng + 5 * Cn * Fn, nbet + 5 * Cn * Fn, w3, ffnB);
    ffn4_write<<<nElemBlocks, 256>>>(ffnB, w4, hB, x, out);
}